// round 2
// baseline (speedup 1.0000x reference)
#include <cuda_runtime.h>
#include <math.h>

// Problem constants
#define BB 4
#define TT 2048
#define HH 16
#define DH 64
#define DM 1024

// Scratch (device globals — no allocation allowed)
__device__ float g_qkv[(size_t)BB * TT * 3 * DM];   // [B,T, 3*1024]  (q|k|v per token)
__device__ float g_Q[(size_t)BB * HH * TT * DH];    // [B,H,T,dh] rope'd
__device__ float g_K[(size_t)BB * HH * TT * DH];
__device__ float g_V[(size_t)BB * HH * TT * DH];
__device__ float g_attn[(size_t)BB * TT * DM];      // [B,T,C] attention output

// ---------------------------------------------------------------------------
// Generic fp32 GEMM: C[M,N] = A[M,K] @ B[K,N] (+bias). M = gridDim.y*128.
// If A == nullptr use g_attn; if C == nullptr use g_qkv (avoids symbol lookup).
// BM=BN=128, BK=8, 256 threads, 8x8 per-thread microtile.
// ---------------------------------------------------------------------------
__global__ void __launch_bounds__(256) gemm128(const float* __restrict__ A,
                                               const float* __restrict__ Bm,
                                               float* __restrict__ C,
                                               const float* __restrict__ bias,
                                               int N, int K)
{
    const float* Ap = A ? A : g_attn;
    float*       Cp = C ? C : g_qkv;

    __shared__ float As[8][128];
    __shared__ float Bs[8][128];

    int tid  = threadIdx.x;
    int br   = blockIdx.y;
    int bc   = blockIdx.x;
    int trow = tid >> 4;        // 0..15
    int tcol = tid & 15;        // 0..15

    float acc[8][8];
#pragma unroll
    for (int i = 0; i < 8; i++)
#pragma unroll
        for (int j = 0; j < 8; j++) acc[i][j] = 0.f;

    int aRow = tid >> 1;            // 0..127
    int aCol = (tid & 1) * 4;       // 0 or 4
    int bRow = tid >> 5;            // 0..7
    int bCol = (tid & 31) * 4;      // 0..124

    const float* Aptr = Ap + (size_t)(br * 128 + aRow) * K + aCol;
    const float* Bptr = Bm + (size_t)bRow * N + bc * 128 + bCol;

    for (int k0 = 0; k0 < K; k0 += 8) {
        float4 a4 = *(const float4*)(Aptr + k0);
        As[aCol + 0][aRow] = a4.x;
        As[aCol + 1][aRow] = a4.y;
        As[aCol + 2][aRow] = a4.z;
        As[aCol + 3][aRow] = a4.w;
        *(float4*)&Bs[bRow][bCol] = *(const float4*)(Bptr + (size_t)k0 * N);
        __syncthreads();

#pragma unroll
        for (int k = 0; k < 8; k++) {
            float ar[8], brr[8];
#pragma unroll
            for (int i = 0; i < 8; i++) ar[i] = As[k][trow * 8 + i];
#pragma unroll
            for (int j = 0; j < 8; j++) brr[j] = Bs[k][tcol * 8 + j];
#pragma unroll
            for (int i = 0; i < 8; i++)
#pragma unroll
                for (int j = 0; j < 8; j++) acc[i][j] += ar[i] * brr[j];
        }
        __syncthreads();
    }

#pragma unroll
    for (int i = 0; i < 8; i++) {
        int row = br * 128 + trow * 8 + i;
        float* cpt = Cp + (size_t)row * N + bc * 128 + tcol * 8;
#pragma unroll
        for (int j = 0; j < 8; j += 4) {
            float4 v;
            int col = bc * 128 + tcol * 8 + j;
            float b0 = bias ? bias[col + 0] : 0.f;
            float b1 = bias ? bias[col + 1] : 0.f;
            float b2 = bias ? bias[col + 2] : 0.f;
            float b3 = bias ? bias[col + 3] : 0.f;
            v.x = acc[i][j + 0] + b0;
            v.y = acc[i][j + 1] + b1;
            v.z = acc[i][j + 2] + b2;
            v.w = acc[i][j + 3] + b3;
            *(float4*)(cpt + j) = v;
        }
    }
}

// ---------------------------------------------------------------------------
// RoPE + scatter: g_qkv [B,T,3,H,dh] -> g_Q/g_K/g_V [B,H,T,dh], rope on Q,K.
// One thread per (b,t,h,pair). 4*2048*16*32 = 2^22 threads.
// ---------------------------------------------------------------------------
__global__ void __launch_bounds__(256) rope_kernel()
{
    int e = blockIdx.x * 256 + threadIdx.x;
    int i = e & 31;
    int h = (e >> 5) & 15;
    int t = (e >> 9) & 2047;
    int b = e >> 20;

    float inv_freq = 1.0f / powf(10000.0f, (float)i * (1.0f / 32.0f));
    float ang = (float)t * inv_freq;
    float sn, cs;
    sincosf(ang, &sn, &cs);

    const float* base = g_qkv + ((size_t)(b * TT + t)) * (3 * DM);
    int off = h * 64 + 2 * i;
    float qe = base[off],        qo = base[off + 1];
    float ke = base[DM + off],   ko = base[DM + off + 1];
    float ve = base[2*DM + off], vo = base[2*DM + off + 1];

    size_t oidx = (((size_t)(b * HH + h)) * TT + t) * DH + 2 * i;
    g_Q[oidx]     = qe * cs - qo * sn;
    g_Q[oidx + 1] = qe * sn + qo * cs;
    g_K[oidx]     = ke * cs - ko * sn;
    g_K[oidx + 1] = ke * sn + ko * cs;
    g_V[oidx]     = ve;
    g_V[oidx + 1] = vo;
}

// ---------------------------------------------------------------------------
// Process one 32-key chunk held in Ks/Vs against one query (4-lane group).
// MODE 0: phase B (gathered global keys), valid iff c < lim.
// MODE 1: phase A (contiguous keys from c0), sparse mask.
// Lane owns 16 dims (dbase). Scores are computed cooperatively (dim-split +
// shuffle reduce); lane cl retains scores for keys c with (c&3)==cl.
// ---------------------------------------------------------------------------
template<int MODE>
__device__ __forceinline__ void chunk_update(
    const float (*Ks)[68], const float (*Vs)[68],
    const float* Qr, int lim, int c0, int qi,
    int cl, int dbase, float& m, float& l, float* o)
{
    float sv[8];
    float rmax = -INFINITY;

#pragma unroll
    for (int c = 0; c < 32; c++) {
        bool valid;
        if (MODE == 0) {
            valid = (c < lim);
        } else {
            int ki = c0 + c;
            valid = (ki <= qi) && (((qi - ki) <= 127) || ((ki & 63) == 0));
        }
        float acc = 0.f;
        if (valid) {
#pragma unroll
            for (int d4 = 0; d4 < 16; d4 += 4) {
                float4 kv = *(const float4*)&Ks[c][dbase + d4];
                acc = fmaf(Qr[d4 + 0], kv.x, acc);
                acc = fmaf(Qr[d4 + 1], kv.y, acc);
                acc = fmaf(Qr[d4 + 2], kv.z, acc);
                acc = fmaf(Qr[d4 + 3], kv.w, acc);
            }
        }
        // full-warp converged shuffles (valid varies only per-group; shuffles
        // are outside the guarded region)
        acc += __shfl_xor_sync(0xffffffffu, acc, 1);
        acc += __shfl_xor_sync(0xffffffffu, acc, 2);
        float s = valid ? acc * 0.125f : -1e9f;   // 1/sqrt(64)
        rmax = fmaxf(rmax, s);
        if ((c & 3) == cl) sv[c >> 2] = s;
    }

    float mnew  = fmaxf(m, rmax);           // finite: every first chunk has a valid key
    float scale = __expf(m - mnew);         // first chunk: expf(-inf)=0

    float ps[8];
    float psum = 0.f;
#pragma unroll
    for (int j = 0; j < 8; j++) {
        float p = __expf(sv[j] - mnew);     // invalid: expf(~-1e9)=0
        ps[j] = p;
        psum += p;
    }
    psum += __shfl_xor_sync(0xffffffffu, psum, 1);
    psum += __shfl_xor_sync(0xffffffffu, psum, 2);
    l = l * scale + psum;
    m = mnew;
#pragma unroll
    for (int d = 0; d < 16; d++) o[d] *= scale;

#pragma unroll
    for (int k = 0; k < 32; k++) {
        float p = __shfl_sync(0xffffffffu, ps[k >> 2], k & 3, 4);
        if (p != 0.f) {
#pragma unroll
            for (int d4 = 0; d4 < 16; d4 += 4) {
                float4 v = *(const float4*)&Vs[k][dbase + d4];
                o[d4 + 0] = fmaf(p, v.x, o[d4 + 0]);
                o[d4 + 1] = fmaf(p, v.y, o[d4 + 1]);
                o[d4 + 2] = fmaf(p, v.z, o[d4 + 2]);
                o[d4 + 3] = fmaf(p, v.w, o[d4 + 3]);
            }
        }
    }
}

// ---------------------------------------------------------------------------
// Main sparse attention. Block = 256 threads = (b, h, 64-query tile).
// Phase B: gathered global keys ki=64g below the local window (all-allowed).
// Phase A: 6 contiguous 32-key chunks covering [q0-128, q0+63] with mask.
// Global-query rows (r==0) are recomputed by attn_global afterwards.
// ---------------------------------------------------------------------------
__global__ void __launch_bounds__(256) attn_main()
{
    int tile = blockIdx.x, h = blockIdx.y, b = blockIdx.z;
    int q0 = tile << 6;
    int tid = threadIdx.x;
    int r = tid >> 2, cl = tid & 3, dbase = cl << 4;
    int qi = q0 + r;

    __shared__ float Ks[32][68];
    __shared__ float Vs[32][68];

    const float* Qb = g_Q + ((size_t)(b * HH + h)) * TT * DH;
    const float* Kb = g_K + ((size_t)(b * HH + h)) * TT * DH;
    const float* Vb = g_V + ((size_t)(b * HH + h)) * TT * DH;

    float Qr[16];
#pragma unroll
    for (int d4 = 0; d4 < 16; d4 += 4)
        *(float4*)&Qr[d4] = *(const float4*)&Qb[(size_t)qi * 64 + dbase + d4];

    float m = -INFINITY, l = 0.f;
    float o[16];
#pragma unroll
    for (int d = 0; d < 16; d++) o[d] = 0.f;

    int krow = tid >> 3, kcol = (tid & 7) << 3;

    int cA0 = (q0 >= 128) ? (q0 - 128) : 0;   // phase A start (mult of 64)
    int Gn  = cA0 >> 6;                        // # global keys below cA0

    // ---- Phase B: gathered global keys ----
    if (Gn > 0) {
        if (krow < Gn) {
            size_t src = ((size_t)(krow << 6)) * 64 + kcol;   // key ki = 64*krow
            *(float4*)&Ks[krow][kcol]     = *(const float4*)&Kb[src];
            *(float4*)&Ks[krow][kcol + 4] = *(const float4*)&Kb[src + 4];
            *(float4*)&Vs[krow][kcol]     = *(const float4*)&Vb[src];
            *(float4*)&Vs[krow][kcol + 4] = *(const float4*)&Vb[src + 4];
        }
        __syncthreads();
        chunk_update<0>(Ks, Vs, Qr, Gn, 0, qi, cl, dbase, m, l, o);
    }

    // ---- Phase A: local window chunks ----
    for (int c0 = cA0; c0 < q0 + 64; c0 += 32) {
        __syncthreads();   // protect Ks/Vs from previous chunk's readers
        size_t src = ((size_t)(c0 + krow)) * 64 + kcol;
        *(float4*)&Ks[krow][kcol]     = *(const float4*)&Kb[src];
        *(float4*)&Ks[krow][kcol + 4] = *(const float4*)&Kb[src + 4];
        *(float4*)&Vs[krow][kcol]     = *(const float4*)&Vb[src];
        *(float4*)&Vs[krow][kcol + 4] = *(const float4*)&Vb[src + 4];
        __syncthreads();
        chunk_update<1>(Ks, Vs, Qr, 32, c0, qi, cl, dbase, m, l, o);
    }

    float inv_l = 1.0f / l;
    float* Ob = g_attn + ((size_t)(b * TT + qi)) * DM + h * 64 + dbase;
#pragma unroll
    for (int d4 = 0; d4 < 16; d4 += 4) {
        float4 v;
        v.x = o[d4 + 0] * inv_l;
        v.y = o[d4 + 1] * inv_l;
        v.z = o[d4 + 2] * inv_l;
        v.w = o[d4 + 3] * inv_l;
        *(float4*)&Ob[d4] = v;
    }
}

// ---------------------------------------------------------------------------
// Global-query rows: qi = 64*j get the FULL causal row. One block per
// (j, h, b). 64 key-groups of 4 lanes each; per-group online softmax over
// strided keys; block-level merge at the end. Overwrites attn_main's r==0 rows.
// ---------------------------------------------------------------------------
__global__ void __launch_bounds__(256) attn_global()
{
    int j = blockIdx.x, h = blockIdx.y, b = blockIdx.z;
    int qi = j << 6;
    int tid = threadIdx.x;
    int g = tid >> 2, cl = tid & 3, dbase = cl << 4;

    const float* Qb = g_Q + ((size_t)(b * HH + h)) * TT * DH;
    const float* Kb = g_K + ((size_t)(b * HH + h)) * TT * DH;
    const float* Vb = g_V + ((size_t)(b * HH + h)) * TT * DH;

    float Qr[16];
#pragma unroll
    for (int d4 = 0; d4 < 16; d4 += 4)
        *(float4*)&Qr[d4] = *(const float4*)&Qb[(size_t)qi * 64 + dbase + d4];

    float m = -INFINITY, l = 0.f;
    float o[16];
#pragma unroll
    for (int d = 0; d < 16; d++) o[d] = 0.f;

    for (int k0 = 0; k0 <= qi; k0 += 64) {
        int k = k0 + g;
        bool valid = (k <= qi);
        float acc = 0.f;
        if (valid) {
#pragma unroll
            for (int d4 = 0; d4 < 16; d4 += 4) {
                float4 kv = *(const float4*)&Kb[(size_t)k * 64 + dbase + d4];
                acc = fmaf(Qr[d4 + 0], kv.x, acc);
                acc = fmaf(Qr[d4 + 1], kv.y, acc);
                acc = fmaf(Qr[d4 + 2], kv.z, acc);
                acc = fmaf(Qr[d4 + 3], kv.w, acc);
            }
        }
        acc += __shfl_xor_sync(0xffffffffu, acc, 1);
        acc += __shfl_xor_sync(0xffffffffu, acc, 2);
        if (valid) {
            float s = acc * 0.125f;
            float mnew = fmaxf(m, s);
            float sc = __expf(m - mnew);       // first key: expf(-inf)=0
            float p  = __expf(s - mnew);
            l = l * sc + p;
            m = mnew;
#pragma unroll
            for (int d4 = 0; d4 < 16; d4 += 4) {
                float4 v = *(const float4*)&Vb[(size_t)k * 64 + dbase + d4];
                o[d4 + 0] = fmaf(o[d4 + 0], sc, p * v.x);
                o[d4 + 1] = fmaf(o[d4 + 1], sc, p * v.y);
                o[d4 + 2] = fmaf(o[d4 + 2], sc, p * v.z);
                o[d4 + 3] = fmaf(o[d4 + 3], sc, p * v.w);
            }
        }
    }

    // ---- merge 64 groups ----
    __shared__ float sm_m[64];
    __shared__ float sm_l[64];
    __shared__ float sm_o[64][64];

    if (cl == 0) { sm_m[g] = m; sm_l[g] = l; }
    __syncthreads();

    float M = -INFINITY;
#pragma unroll 8
    for (int g2 = 0; g2 < 64; g2++) M = fmaxf(M, sm_m[g2]);

    float fac = __expf(m - M);                 // m=-inf -> 0
#pragma unroll
    for (int d = 0; d < 16; d++) sm_o[g][dbase + d] = o[d] * fac;
    __syncthreads();

    for (int s = 32; s > 0; s >>= 1) {
        if (g < s) {
#pragma unroll
            for (int d4 = 0; d4 < 16; d4 += 4) {
                float4 a = *(float4*)&sm_o[g][dbase + d4];
                float4 bb = *(float4*)&sm_o[g + s][dbase + d4];
                a.x += bb.x; a.y += bb.y; a.z += bb.z; a.w += bb.w;
                *(float4*)&sm_o[g][dbase + d4] = a;
            }
        }
        __syncthreads();
    }

    float l_tot = 0.f;
#pragma unroll 8
    for (int g2 = 0; g2 < 64; g2++) l_tot += sm_l[g2] * __expf(sm_m[g2] - M);

    if (g == 0) {
        float inv = 1.0f / l_tot;
        float* Ob = g_attn + ((size_t)(b * TT + qi)) * DM + h * 64 + dbase;
#pragma unroll
        for (int d4 = 0; d4 < 16; d4 += 4) {
            float4 v = *(float4*)&sm_o[0][dbase + d4];
            v.x *= inv; v.y *= inv; v.z *= inv; v.w *= inv;
            *(float4*)&Ob[d4] = v;
        }
    }
}

// ---------------------------------------------------------------------------
extern "C" void kernel_launch(void* const* d_in, const int* in_sizes, int n_in,
                              void* d_out, int out_size)
{
    const float* x    = (const float*)d_in[0];   // [4,2048,1024]
    const float* Wqkv = (const float*)d_in[1];   // [1024,3072]
    const float* Wout = (const float*)d_in[2];   // [1024,1024]
    const float* bout = (const float*)d_in[3];   // [1024]
    float* out = (float*)d_out;                  // [4,2048,1024]

    dim3 blk(256);

    // 1) qkv = x @ W_qkv   (M=8192, N=3072, K=1024) -> g_qkv (C==nullptr)
    gemm128<<<dim3(24, 64), blk>>>(x, Wqkv, nullptr, nullptr, 3072, 1024);

    // 2) RoPE + scatter into [B,H,T,dh]
    rope_kernel<<<16384, 256>>>();

    // 3) sparse attention -> g_attn [B,T,C]  (r==0 rows overwritten by 3b)
    attn_main<<<dim3(32, 16, 4), blk>>>();

    // 3b) full causal rows for global queries
    attn_global<<<dim3(32, 16, 4), blk>>>();

    // 4) out = g_attn @ W_out + b_out  (A==nullptr -> g_attn)
    gemm128<<<dim3(8, 64), blk>>>(nullptr, Wout, out, bout, 1024, 1024);
}

// round 10
// speedup vs baseline: 1.1545x; 1.1545x over previous
#include <cuda_runtime.h>
#include <cuda_bf16.h>
#include <math.h>
#include <stdint.h>

// Problem constants
#define BB 4
#define TT 2048
#define HH 16
#define DH 64
#define DM 1024

// bf16-split GEMM config
#define KEFF 3072          // 3 * 1024 (hi|hi|lo split along K)
#define BK 32              // bf16 K per stage
#define NKIT (KEFF / BK)   // 96
#define PITCH 80           // smem row pitch bytes (64 data + 16 pad)
#define OP_BYTES (128 * PITCH)          // 10240 per operand tile
#define STAGE_BYTES (2 * OP_BYTES)      // 20480
#define STAGES 3
#define SMEM_DYN (STAGES * STAGE_BYTES) // 61440

// Scratch (device globals — no allocation allowed)
__device__ float g_qkv[(size_t)BB * TT * 3 * DM];   // [B,T, 3*1024]
__device__ float g_Q[(size_t)BB * HH * TT * DH];    // [B,H,T,dh] rope'd
__device__ float g_K[(size_t)BB * HH * TT * DH];
__device__ float g_V[(size_t)BB * HH * TT * DH];
__device__ float g_attn[(size_t)BB * TT * DM];      // [B,T,C] attention output
__device__ __nv_bfloat16 g_Xs[(size_t)BB * TT * KEFF];    // split activations [8192,3072]
__device__ __nv_bfloat16 g_Wqs[(size_t)3 * DM * KEFF];    // split W_qkv^T [3072,3072]
__device__ __nv_bfloat16 g_Wos[(size_t)DM * KEFF];        // split W_out^T [1024,3072]

// ---------------------------------------------------------------------------
// PTX helpers (compute_103-safe: cp.async + ldmatrix + mma.sync only)
// ---------------------------------------------------------------------------
__device__ __forceinline__ uint32_t s2u(const void* p) {
    return (uint32_t)__cvta_generic_to_shared(p);
}
__device__ __forceinline__ void cp16(uint32_t dst, const void* src) {
    asm volatile("cp.async.cg.shared.global [%0], [%1], 16;\n" :: "r"(dst), "l"(src));
}
#define CP_COMMIT() asm volatile("cp.async.commit_group;\n")
#define CP_WAIT(n)  asm volatile("cp.async.wait_group %0;\n" :: "n"(n))

__device__ __forceinline__ void ldm_x4(uint32_t& r0, uint32_t& r1,
                                       uint32_t& r2, uint32_t& r3, uint32_t addr) {
    asm volatile("ldmatrix.sync.aligned.m8n8.x4.shared.b16 {%0,%1,%2,%3}, [%4];"
                 : "=r"(r0), "=r"(r1), "=r"(r2), "=r"(r3) : "r"(addr));
}
__device__ __forceinline__ void mma16816(float* c, const uint32_t* a, const uint32_t* b) {
    asm volatile(
        "mma.sync.aligned.m16n8k16.row.col.f32.bf16.bf16.f32 "
        "{%0,%1,%2,%3}, {%4,%5,%6,%7}, {%8,%9}, {%0,%1,%2,%3};"
        : "+f"(c[0]), "+f"(c[1]), "+f"(c[2]), "+f"(c[3])
        : "r"(a[0]), "r"(a[1]), "r"(a[2]), "r"(a[3]), "r"(b[0]), "r"(b[1]));
}

// ---------------------------------------------------------------------------
// Prep: fp32 [M,1024] -> bf16 split [M,3072] = [hi | hi | lo]
// src == nullptr -> g_attn
// ---------------------------------------------------------------------------
__global__ void __launch_bounds__(256) prep_split(const float* __restrict__ src)
{
    const float* s = src ? src : g_attn;
    int i = blockIdx.x * 256 + threadIdx.x;      // < 8192*1024
    int row = i >> 10, k = i & 1023;
    float v = s[i];
    __nv_bfloat16 hi = __float2bfloat16(v);
    __nv_bfloat16 lo = __float2bfloat16(v - __bfloat162float(hi));
    size_t base = (size_t)row * KEFF;
    g_Xs[base + k]        = hi;
    g_Xs[base + 1024 + k] = hi;
    g_Xs[base + 2048 + k] = lo;
}

// ---------------------------------------------------------------------------
// Prep weights: W [1024, Ndim] row-major -> out [Ndim, 3072] bf16, K-major,
// out[n][0:1024]=hi(W[k][n]), [1024:2048]=lo, [2048:3072]=hi.
// ---------------------------------------------------------------------------
__global__ void __launch_bounds__(256) prep_Wt(const float* __restrict__ W, int Ndim, int sel)
{
    __shared__ float tile[32][33];
    __nv_bfloat16* out = sel ? g_Wos : g_Wqs;
    int n0 = blockIdx.x * 32, k0 = blockIdx.y * 32;
    int tx = threadIdx.x, ty = threadIdx.y;
#pragma unroll
    for (int j = 0; j < 32; j += 8)
        tile[ty + j][tx] = W[(size_t)(k0 + ty + j) * Ndim + n0 + tx];
    __syncthreads();
#pragma unroll
    for (int j = 0; j < 32; j += 8) {
        float v = tile[tx][ty + j];              // = W[k0+tx][n0+ty+j]
        int n = n0 + ty + j, k = k0 + tx;
        __nv_bfloat16 hi = __float2bfloat16(v);
        __nv_bfloat16 lo = __float2bfloat16(v - __bfloat162float(hi));
        size_t b = (size_t)n * KEFF;
        out[b + k]        = hi;
        out[b + 1024 + k] = lo;
        out[b + 2048 + k] = hi;
    }
}

// ---------------------------------------------------------------------------
// bf16 mma.sync GEMM: C[M,N] = A'[M,3072] @ B'[N,3072]^T, fp32 accum.
// CTA 128x128, warp 64x32 (8 warps), BK=32, 3-stage cp.async.
// ---------------------------------------------------------------------------
__device__ __forceinline__ void load_stage(uint32_t bufs, int stage,
                                           const __nv_bfloat16* Ab,
                                           const __nv_bfloat16* Bb,
                                           int c, int tid)
{
    uint32_t sA = bufs + stage * STAGE_BYTES;
    const __nv_bfloat16* src;
    uint32_t dst;
    int row;
    if (tid < 128) { row = tid; src = Ab + (size_t)row * KEFF + c * BK; dst = sA + row * PITCH; }
    else { row = tid - 128; src = Bb + (size_t)row * KEFF + c * BK; dst = sA + OP_BYTES + row * PITCH; }
#pragma unroll
    for (int j = 0; j < 4; j++) cp16(dst + j * 16, src + j * 8);
    CP_COMMIT();
}

__global__ void __launch_bounds__(256) gemm_mma(float* __restrict__ Cout,
                                                const float* __restrict__ bias,
                                                int N, int sel)
{
    extern __shared__ char dsmem[];
    const __nv_bfloat16* Ab = g_Xs + (size_t)(blockIdx.y * 128) * KEFF;
    const __nv_bfloat16* Bw = sel ? g_Wos : g_Wqs;
    const __nv_bfloat16* Bb = Bw + (size_t)(blockIdx.x * 128) * KEFF;
    float* Cp = sel ? Cout : g_qkv;

    uint32_t bufs = s2u(dsmem);
    int tid = threadIdx.x, wid = tid >> 5, lane = tid & 31;
    int wm = (wid >> 2) * 64;      // warp M offset (0 or 64)
    int wn = (wid & 3) * 32;       // warp N offset (0,32,64,96)

    float acc[4][4][4];            // [mt][nf][frag]
#pragma unroll
    for (int i = 0; i < 4; i++)
#pragma unroll
        for (int j = 0; j < 4; j++)
#pragma unroll
            for (int f = 0; f < 4; f++) acc[i][j][f] = 0.f;

    int aRow = (lane & 15);                 // row within 16-row A block
    int aCB  = (lane >> 4) << 4;            // +16B for k8-15 half
    int bg   = lane >> 3;                   // 0..3
    int bRow = ((bg & 2) << 2) + (lane & 7);// n offset within 16
    int bCB  = (bg & 1) << 4;               // +16B for k8-15 half

    // prologue
    load_stage(bufs, 0, Ab, Bb, 0, tid);
    load_stage(bufs, 1, Ab, Bb, 1, tid);

    for (int c = 0; c < NKIT; c++) {
        CP_WAIT(1);                 // stage c resident
        __syncthreads();            // all compute on stage (c-1) finished

        if (c + 2 < NKIT) load_stage(bufs, (c + 2) % STAGES, Ab, Bb, c + 2, tid);
        else CP_COMMIT();           // keep wait_group counts consistent

        uint32_t sA = bufs + (c % STAGES) * STAGE_BYTES;
        uint32_t sB = sA + OP_BYTES;

#pragma unroll
        for (int ks = 0; ks < 2; ks++) {
            int kb = ks * 32;       // byte offset of this k16 within 64B row
            uint32_t a[4][4];
#pragma unroll
            for (int mt = 0; mt < 4; mt++) {
                uint32_t addr = sA + (wm + mt * 16 + aRow) * PITCH + kb + aCB;
                ldm_x4(a[mt][0], a[mt][1], a[mt][2], a[mt][3], addr);
            }
            uint32_t bfr[4][2];
#pragma unroll
            for (int nt = 0; nt < 2; nt++) {
                uint32_t r0, r1, r2, r3;
                uint32_t addr = sB + (wn + nt * 16 + bRow) * PITCH + kb + bCB;
                ldm_x4(r0, r1, r2, r3, addr);
                bfr[nt * 2 + 0][0] = r0; bfr[nt * 2 + 0][1] = r1;
                bfr[nt * 2 + 1][0] = r2; bfr[nt * 2 + 1][1] = r3;
            }
#pragma unroll
            for (int mt = 0; mt < 4; mt++)
#pragma unroll
                for (int nf = 0; nf < 4; nf++)
                    mma16816(acc[mt][nf], a[mt], bfr[nf]);
        }
    }

    // epilogue: lane l holds (m=l/4, n=(l%4)*2) and (m+8, n)
    int ml = lane >> 2, nl = (lane & 3) * 2;
#pragma unroll
    for (int mt = 0; mt < 4; mt++) {
#pragma unroll
        for (int nf = 0; nf < 4; nf++) {
            int col = blockIdx.x * 128 + wn + nf * 8 + nl;
            float b0 = bias ? bias[col]     : 0.f;
            float b1 = bias ? bias[col + 1] : 0.f;
            int r0 = blockIdx.y * 128 + wm + mt * 16 + ml;
            float2 v0 = { acc[mt][nf][0] + b0, acc[mt][nf][1] + b1 };
            float2 v1 = { acc[mt][nf][2] + b0, acc[mt][nf][3] + b1 };
            *(float2*)(Cp + (size_t)r0 * N + col)       = v0;
            *(float2*)(Cp + (size_t)(r0 + 8) * N + col) = v1;
        }
    }
}

// ---------------------------------------------------------------------------
// RoPE + scatter: g_qkv [B,T,3,H,dh] -> g_Q/g_K/g_V [B,H,T,dh], rope on Q,K.
// ---------------------------------------------------------------------------
__global__ void __launch_bounds__(256) rope_kernel()
{
    int e = blockIdx.x * 256 + threadIdx.x;
    int i = e & 31;
    int h = (e >> 5) & 15;
    int t = (e >> 9) & 2047;
    int b = e >> 20;

    float inv_freq = 1.0f / powf(10000.0f, (float)i * (1.0f / 32.0f));
    float ang = (float)t * inv_freq;
    float sn, cs;
    sincosf(ang, &sn, &cs);

    const float* base = g_qkv + ((size_t)(b * TT + t)) * (3 * DM);
    int off = h * 64 + 2 * i;
    float qe = base[off],          qo = base[off + 1];
    float ke = base[DM + off],     ko = base[DM + off + 1];
    float ve = base[2 * DM + off], vo = base[2 * DM + off + 1];

    size_t oidx = (((size_t)(b * HH + h)) * TT + t) * DH + 2 * i;
    g_Q[oidx]     = qe * cs - qo * sn;
    g_Q[oidx + 1] = qe * sn + qo * cs;
    g_K[oidx]     = ke * cs - ko * sn;
    g_K[oidx + 1] = ke * sn + ko * cs;
    g_V[oidx]     = ve;
    g_V[oidx + 1] = vo;
}

// ---------------------------------------------------------------------------
// Sparse attention chunk update (unchanged — passed at 1.25e-6)
// ---------------------------------------------------------------------------
template<int MODE>
__device__ __forceinline__ void chunk_update(
    const float (*Ks)[68], const float (*Vs)[68],
    const float* Qr, int lim, int c0, int qi,
    int cl, int dbase, float& m, float& l, float* o)
{
    float sv[8];
    float rmax = -INFINITY;

#pragma unroll
    for (int c = 0; c < 32; c++) {
        bool valid;
        if (MODE == 0) {
            valid = (c < lim);
        } else {
            int ki = c0 + c;
            valid = (ki <= qi) && (((qi - ki) <= 127) || ((ki & 63) == 0));
        }
        float acc = 0.f;
        if (valid) {
#pragma unroll
            for (int d4 = 0; d4 < 16; d4 += 4) {
                float4 kv = *(const float4*)&Ks[c][dbase + d4];
                acc = fmaf(Qr[d4 + 0], kv.x, acc);
                acc = fmaf(Qr[d4 + 1], kv.y, acc);
                acc = fmaf(Qr[d4 + 2], kv.z, acc);
                acc = fmaf(Qr[d4 + 3], kv.w, acc);
            }
        }
        acc += __shfl_xor_sync(0xffffffffu, acc, 1);
        acc += __shfl_xor_sync(0xffffffffu, acc, 2);
        float s = valid ? acc * 0.125f : -1e9f;
        rmax = fmaxf(rmax, s);
        if ((c & 3) == cl) sv[c >> 2] = s;
    }

    float mnew  = fmaxf(m, rmax);
    float scale = __expf(m - mnew);

    float ps[8];
    float psum = 0.f;
#pragma unroll
    for (int j = 0; j < 8; j++) {
        float p = __expf(sv[j] - mnew);
        ps[j] = p;
        psum += p;
    }
    psum += __shfl_xor_sync(0xffffffffu, psum, 1);
    psum += __shfl_xor_sync(0xffffffffu, psum, 2);
    l = l * scale + psum;
    m = mnew;
#pragma unroll
    for (int d = 0; d < 16; d++) o[d] *= scale;

#pragma unroll
    for (int k = 0; k < 32; k++) {
        float p = __shfl_sync(0xffffffffu, ps[k >> 2], k & 3, 4);
        if (p != 0.f) {
#pragma unroll
            for (int d4 = 0; d4 < 16; d4 += 4) {
                float4 v = *(const float4*)&Vs[k][dbase + d4];
                o[d4 + 0] = fmaf(p, v.x, o[d4 + 0]);
                o[d4 + 1] = fmaf(p, v.y, o[d4 + 1]);
                o[d4 + 2] = fmaf(p, v.z, o[d4 + 2]);
                o[d4 + 3] = fmaf(p, v.w, o[d4 + 3]);
            }
        }
    }
}

__global__ void __launch_bounds__(256) attn_main()
{
    int tile = blockIdx.x, h = blockIdx.y, b = blockIdx.z;
    int q0 = tile << 6;
    int tid = threadIdx.x;
    int r = tid >> 2, cl = tid & 3, dbase = cl << 4;
    int qi = q0 + r;

    __shared__ float Ks[32][68];
    __shared__ float Vs[32][68];

    const float* Qb = g_Q + ((size_t)(b * HH + h)) * TT * DH;
    const float* Kb = g_K + ((size_t)(b * HH + h)) * TT * DH;
    const float* Vb = g_V + ((size_t)(b * HH + h)) * TT * DH;

    float Qr[16];
#pragma unroll
    for (int d4 = 0; d4 < 16; d4 += 4)
        *(float4*)&Qr[d4] = *(const float4*)&Qb[(size_t)qi * 64 + dbase + d4];

    float m = -INFINITY, l = 0.f;
    float o[16];
#pragma unroll
    for (int d = 0; d < 16; d++) o[d] = 0.f;

    int krow = tid >> 3, kcol = (tid & 7) << 3;

    int cA0 = (q0 >= 128) ? (q0 - 128) : 0;
    int Gn  = cA0 >> 6;

    if (Gn > 0) {
        if (krow < Gn) {
            size_t src = ((size_t)(krow << 6)) * 64 + kcol;
            *(float4*)&Ks[krow][kcol]     = *(const float4*)&Kb[src];
            *(float4*)&Ks[krow][kcol + 4] = *(const float4*)&Kb[src + 4];
            *(float4*)&Vs[krow][kcol]     = *(const float4*)&Vb[src];
            *(float4*)&Vs[krow][kcol + 4] = *(const float4*)&Vb[src + 4];
        }
        __syncthreads();
        chunk_update<0>(Ks, Vs, Qr, Gn, 0, qi, cl, dbase, m, l, o);
    }

    for (int c0 = cA0; c0 < q0 + 64; c0 += 32) {
        __syncthreads();
        size_t src = ((size_t)(c0 + krow)) * 64 + kcol;
        *(float4*)&Ks[krow][kcol]     = *(const float4*)&Kb[src];
        *(float4*)&Ks[krow][kcol + 4] = *(const float4*)&Kb[src + 4];
        *(float4*)&Vs[krow][kcol]     = *(const float4*)&Vb[src];
        *(float4*)&Vs[krow][kcol + 4] = *(const float4*)&Vb[src + 4];
        __syncthreads();
        chunk_update<1>(Ks, Vs, Qr, 32, c0, qi, cl, dbase, m, l, o);
    }

    float inv_l = 1.0f / l;
    float* Ob = g_attn + ((size_t)(b * TT + qi)) * DM + h * 64 + dbase;
#pragma unroll
    for (int d4 = 0; d4 < 16; d4 += 4) {
        float4 v;
        v.x = o[d4 + 0] * inv_l;
        v.y = o[d4 + 1] * inv_l;
        v.z = o[d4 + 2] * inv_l;
        v.w = o[d4 + 3] * inv_l;
        *(float4*)&Ob[d4] = v;
    }
}

// ---------------------------------------------------------------------------
// Global-query rows, shared-stream version. One block per (h, b); the 32
// global queries qi = 64j of that (b,h) share a single K/V stream through
// smem. 8 lanes per query, 8 dims per lane. Guarded online softmax; per-warp
// early skip once c0 exceeds the warp's max qi. Overwrites r==0 rows.
// ---------------------------------------------------------------------------
__global__ void __launch_bounds__(256) attn_global()
{
    int h = blockIdx.x, b = blockIdx.y;
    int tid = threadIdx.x;
    int q    = tid >> 3;          // 0..31 -> qi = 64q
    int sub  = tid & 7;
    int dbase = sub << 3;         // 8 dims per lane
    int qi   = q << 6;

    __shared__ float Ks[32][68];
    __shared__ float Vs[32][68];

    const float* Qb = g_Q + ((size_t)(b * HH + h)) * TT * DH;
    const float* Kb = g_K + ((size_t)(b * HH + h)) * TT * DH;
    const float* Vb = g_V + ((size_t)(b * HH + h)) * TT * DH;

    float Qr[8];
    *(float4*)&Qr[0] = *(const float4*)&Qb[(size_t)qi * 64 + dbase];
    *(float4*)&Qr[4] = *(const float4*)&Qb[(size_t)qi * 64 + dbase + 4];

    float m = -INFINITY, l = 0.f;
    float o[8];
#pragma unroll
    for (int d = 0; d < 8; d++) o[d] = 0.f;

    int krow = tid >> 3, kcol = (tid & 7) << 3;
    int wmaxqi = (((tid >> 5) << 2) + 3) << 6;   // max qi among this warp's 4 queries

    for (int c0 = 0; c0 < TT; c0 += 32) {
        __syncthreads();
        size_t src = ((size_t)(c0 + krow)) * 64 + kcol;
        *(float4*)&Ks[krow][kcol]     = *(const float4*)&Kb[src];
        *(float4*)&Ks[krow][kcol + 4] = *(const float4*)&Kb[src + 4];
        *(float4*)&Vs[krow][kcol]     = *(const float4*)&Vb[src];
        *(float4*)&Vs[krow][kcol + 4] = *(const float4*)&Vb[src + 4];
        __syncthreads();

        if (c0 > wmaxqi) continue;     // warp-uniform: no query here needs it

#pragma unroll 4
        for (int k = 0; k < 32; k++) {
            int ki = c0 + k;
            float acc = 0.f;
#pragma unroll
            for (int d4 = 0; d4 < 8; d4 += 4) {
                float4 kv = *(const float4*)&Ks[k][dbase + d4];
                acc = fmaf(Qr[d4 + 0], kv.x, acc);
                acc = fmaf(Qr[d4 + 1], kv.y, acc);
                acc = fmaf(Qr[d4 + 2], kv.z, acc);
                acc = fmaf(Qr[d4 + 3], kv.w, acc);
            }
            acc += __shfl_xor_sync(0xffffffffu, acc, 1);
            acc += __shfl_xor_sync(0xffffffffu, acc, 2);
            acc += __shfl_xor_sync(0xffffffffu, acc, 4);
            if (ki <= qi) {
                float s = acc * 0.125f;
                float mnew = fmaxf(m, s);
                float sc = __expf(m - mnew);   // first key: expf(-inf)=0
                float p  = __expf(s - mnew);
                l = l * sc + p;
                m = mnew;
#pragma unroll
                for (int d4 = 0; d4 < 8; d4 += 4) {
                    float4 v = *(const float4*)&Vs[k][dbase + d4];
                    o[d4 + 0] = fmaf(o[d4 + 0], sc, p * v.x);
                    o[d4 + 1] = fmaf(o[d4 + 1], sc, p * v.y);
                    o[d4 + 2] = fmaf(o[d4 + 2], sc, p * v.z);
                    o[d4 + 3] = fmaf(o[d4 + 3], sc, p * v.w);
                }
            }
        }
    }

    float inv = 1.0f / l;    // l > 0: key 0 is always allowed (ki=0 <= qi)
    float* Ob = g_attn + ((size_t)(b * TT + qi)) * DM + h * 64 + dbase;
    float4 v0 = { o[0] * inv, o[1] * inv, o[2] * inv, o[3] * inv };
    float4 v1 = { o[4] * inv, o[5] * inv, o[6] * inv, o[7] * inv };
    *(float4*)&Ob[0] = v0;
    *(float4*)&Ob[4] = v1;
}

// ---------------------------------------------------------------------------
extern "C" void kernel_launch(void* const* d_in, const int* in_sizes, int n_in,
                              void* d_out, int out_size)
{
    const float* x    = (const float*)d_in[0];   // [4,2048,1024]
    const float* Wqkv = (const float*)d_in[1];   // [1024,3072]
    const float* Wout = (const float*)d_in[2];   // [1024,1024]
    const float* bout = (const float*)d_in[3];   // [1024]
    float* out = (float*)d_out;                  // [4,2048,1024]

    cudaFuncSetAttribute(gemm_mma, cudaFuncAttributeMaxDynamicSharedMemorySize, SMEM_DYN);

    // 0) bf16 split prep
    prep_split<<<32768, 256>>>(x);                          // x -> g_Xs
    prep_Wt<<<dim3(96, 32), dim3(32, 8)>>>(Wqkv, 3072, 0);  // -> g_Wqs
    prep_Wt<<<dim3(32, 32), dim3(32, 8)>>>(Wout, 1024, 1);  // -> g_Wos

    // 1) qkv = x @ W_qkv  (mma.sync bf16x3) -> g_qkv
    gemm_mma<<<dim3(24, 64), 256, SMEM_DYN>>>(nullptr, nullptr, 3072, 0);

    // 2) RoPE + scatter into [B,H,T,dh]
    rope_kernel<<<16384, 256>>>();

    // 3) sparse attention -> g_attn (r==0 rows overwritten by 3b)
    attn_main<<<dim3(32, 16, 4), 256>>>();
    attn_global<<<dim3(16, 4), 256>>>();

    // 4) split g_attn, then out = g_attn @ W_out + b_out
    prep_split<<<32768, 256>>>(nullptr);                    // g_attn -> g_Xs
    gemm_mma<<<dim3(8, 64), 256, SMEM_DYN>>>(out, bout, 1024, 1);
}